// round 17
// baseline (speedup 1.0000x reference)
#include <cuda_runtime.h>
#include <cstdint>
#include <cfloat>

// Problem constants
#define QN    512
#define NLIB  262144
#define DDIM  768
#define KOUT  10
#define KCAND 16

// Quantization
#define QSCALE 20.0f
#define INV_DOT_SCALE (1.0f / (QSCALE * QSCALE))   // dot = acc / 400

// GEMM tiling (int8 IMMA m16n8k32)
#define TM 128
#define TN 128
#define KCH 64                       // int8 k per chunk (two k32 mma steps)
#define NCHUNK (DDIM / KCH)          // 12
#define ROWB 80                      // smem row stride bytes (64B data + 16B pad)
#define MAT_BYTES (128 * ROWB)       // 10240
#define STAGE_BYTES (2 * MAT_BYTES)  // 20480 (A + B)
#define NSTG 4
#define SMEM_BYTES (NSTG * STAGE_BYTES)  // 81920

// ---------------- scratch ----------------
__device__ float g_d2[(size_t)QN * NLIB];                     // 512 MB
__device__ __align__(16) int8_t g_libi[(size_t)NLIB * DDIM];  // 192 MB
__device__ __align__(16) int8_t g_qi[(size_t)QN * DDIM];
__device__ float g_xsq[NLIB];
__device__ float g_qsq[QN];
__device__ int   g_cand[QN * KCAND];

// ---------------- PTX helpers ----------------
__device__ __forceinline__ uint32_t smem_u32(const void* p) {
    uint32_t a;
    asm("{ .reg .u64 t; cvta.to.shared.u64 t, %1; cvt.u32.u64 %0, t; }"
        : "=r"(a) : "l"(p));
    return a;
}
__device__ __forceinline__ void cp16(uint32_t s, const void* g) {
    asm volatile("cp.async.cg.shared.global [%0], [%1], 16;" :: "r"(s), "l"(g));
}
__device__ __forceinline__ void cp_commit() {
    asm volatile("cp.async.commit_group;" ::: "memory");
}
template <int N>
__device__ __forceinline__ void cp_wait() {
    asm volatile("cp.async.wait_group %0;" :: "n"(N) : "memory");
}
__device__ __forceinline__ void ldm4(uint32_t& r0, uint32_t& r1, uint32_t& r2,
                                     uint32_t& r3, uint32_t a) {
    asm volatile("ldmatrix.sync.aligned.m8n8.x4.shared.b16 {%0,%1,%2,%3}, [%4];"
                 : "=r"(r0), "=r"(r1), "=r"(r2), "=r"(r3) : "r"(a));
}
__device__ __forceinline__ void imma16832(int* c, const uint32_t* a, const uint32_t* b) {
    asm volatile(
        "mma.sync.aligned.m16n8k32.row.col.s32.s8.s8.s32 "
        "{%0,%1,%2,%3}, {%4,%5,%6,%7}, {%8,%9}, {%0,%1,%2,%3};"
        : "+r"(c[0]), "+r"(c[1]), "+r"(c[2]), "+r"(c[3])
        : "r"(a[0]), "r"(a[1]), "r"(a[2]), "r"(a[3]), "r"(b[0]), "r"(b[1]));
}
__device__ __forceinline__ uint32_t q8(float x) {
    int v = __float2int_rn(fminf(fmaxf(x * QSCALE, -127.f), 127.f));
    return (uint32_t)v & 0xFFu;
}

// ---------------- fused quantize(fp32->int8) + exact fp32 row norm ----------------
__global__ void convert_kernel(const float* __restrict__ x,
                               int8_t* __restrict__ xq,
                               float* __restrict__ sq, int rows) {
    int gt = blockIdx.x * blockDim.x + threadIdx.x;
    int w = gt >> 5;
    int lane = gt & 31;
    if (w >= rows) return;
    const float4* p = reinterpret_cast<const float4*>(x + (size_t)w * DDIM);
    uint2* o = reinterpret_cast<uint2*>(xq + (size_t)w * DDIM);
    float s = 0.f;
#pragma unroll
    for (int i = lane; i < DDIM / 8; i += 32) {
        float4 v0 = p[2 * i];
        float4 v1 = p[2 * i + 1];
        s = fmaf(v0.x, v0.x, fmaf(v0.y, v0.y, fmaf(v0.z, v0.z, fmaf(v0.w, v0.w, s))));
        s = fmaf(v1.x, v1.x, fmaf(v1.y, v1.y, fmaf(v1.z, v1.z, fmaf(v1.w, v1.w, s))));
        uint2 u;
        u.x = q8(v0.x) | (q8(v0.y) << 8) | (q8(v0.z) << 16) | (q8(v0.w) << 24);
        u.y = q8(v1.x) | (q8(v1.y) << 8) | (q8(v1.z) << 16) | (q8(v1.w) << 24);
        o[i] = u;
    }
#pragma unroll
    for (int off = 16; off; off >>= 1) s += __shfl_xor_sync(0xffffffffu, s, off);
    if (lane == 0) sq[w] = s;
}

// ---------------- int8 IMMA GEMM -> approx d2 ----------------
// d2[m][n] = qsq[m] + xsq[n] - acc[m][n] / 200
__global__ void __launch_bounds__(256, 2) gemm_kernel() {
    extern __shared__ __align__(16) char dyn_smem[];
    const uint32_t sbase = smem_u32(dyn_smem);

    const int tid  = threadIdx.x;
    const int lane = tid & 31;
    const int warp = tid >> 5;
    const int wm = warp >> 2;       // 0..1 (m half)
    const int wn = warp & 3;        // 0..3 (n quarter)
    const int m0 = blockIdx.x * TM; // grid.x = 4 (m fastest -> B shared in L2)
    const int n0 = blockIdx.y * TN;

    // ---- cp.async mapping: per thread 2x16B for A, 2x16B for B per stage ----
    const int crow = tid >> 1;                  // 0..127
    const int cseg = (tid & 1) * 2;             // 0 or 2 (16B segments in 64B row)
    const int8_t* gA = g_qi  + (size_t)(m0 + crow) * DDIM + cseg * 16;
    const int8_t* gB = g_libi + (size_t)(n0 + crow) * DDIM + cseg * 16;
    const uint32_t sD = sbase + crow * ROWB + cseg * 16;

    // ---- ldmatrix smem addresses (80B stride: conflict-free phases) ----
    uint32_t aAddr[4], bAddr[2];
#pragma unroll
    for (int mi = 0; mi < 4; ++mi)
        aAddr[mi] = sbase + (64 * wm + 16 * mi + (lane & 15)) * ROWB + 16 * (lane >> 4);
#pragma unroll
    for (int bi = 0; bi < 2; ++bi)
        bAddr[bi] = sbase + MAT_BYTES
                  + (32 * wn + 16 * bi + ((lane & 7) + 8 * (lane >> 4))) * ROWB
                  + 16 * ((lane >> 3) & 1);

    int acc[4][4][4];
#pragma unroll
    for (int mi = 0; mi < 4; ++mi)
#pragma unroll
        for (int ni = 0; ni < 4; ++ni)
#pragma unroll
            for (int k = 0; k < 4; ++k) acc[mi][ni][k] = 0;

    auto load_stage = [&](int t, int stg) {
        const uint32_t so = sD + stg * STAGE_BYTES;
        const int8_t* a = gA + t * KCH;
        const int8_t* b = gB + t * KCH;
        cp16(so,                  a);
        cp16(so + 16,             a + 16);
        cp16(so + MAT_BYTES,      b);
        cp16(so + MAT_BYTES + 16, b + 16);
        cp_commit();
    };

    // prologue: stages 0..2
    load_stage(0, 0);
    load_stage(1, 1);
    load_stage(2, 2);

#pragma unroll 1
    for (int t = 0; t < NCHUNK; ++t) {
        cp_wait<2>();
        __syncthreads();
        if (t + 3 < NCHUNK) load_stage(t + 3, (t + 3) & (NSTG - 1));

        const uint32_t soff = (t & (NSTG - 1)) * STAGE_BYTES;
#pragma unroll
        for (int ks = 0; ks < 2; ++ks) {
            uint32_t af[4][4], bfr[2][4];
#pragma unroll
            for (int mi = 0; mi < 4; ++mi)
                ldm4(af[mi][0], af[mi][1], af[mi][2], af[mi][3],
                     aAddr[mi] + soff + 32 * ks);
#pragma unroll
            for (int bi = 0; bi < 2; ++bi)
                ldm4(bfr[bi][0], bfr[bi][1], bfr[bi][2], bfr[bi][3],
                     bAddr[bi] + soff + 32 * ks);
#pragma unroll
            for (int mi = 0; mi < 4; ++mi)
#pragma unroll
                for (int ni = 0; ni < 4; ++ni)
                    imma16832(acc[mi][ni], af[mi], &bfr[ni >> 1][(ni & 1) * 2]);
        }
    }

    // ---- epilogue: d2 = qsq + xsq - acc/200 ----
#pragma unroll
    for (int mi = 0; mi < 4; ++mi) {
        const int r0 = m0 + 64 * wm + 16 * mi + (lane >> 2);
        const float qs0 = g_qsq[r0];
        const float qs1 = g_qsq[r0 + 8];
#pragma unroll
        for (int ni = 0; ni < 4; ++ni) {
            const int c0 = n0 + 32 * wn + 8 * ni + 2 * (lane & 3);
            const float2 xs = *reinterpret_cast<const float2*>(&g_xsq[c0]);
            const int* c = acc[mi][ni];
            float2 o0, o1;
            o0.x = fmaf(-2.f * INV_DOT_SCALE, (float)c[0], qs0 + xs.x);
            o0.y = fmaf(-2.f * INV_DOT_SCALE, (float)c[1], qs0 + xs.y);
            o1.x = fmaf(-2.f * INV_DOT_SCALE, (float)c[2], qs1 + xs.x);
            o1.y = fmaf(-2.f * INV_DOT_SCALE, (float)c[3], qs1 + xs.y);
            *reinterpret_cast<float2*>(&g_d2[(size_t)r0 * NLIB + c0]) = o0;
            *reinterpret_cast<float2*>(&g_d2[(size_t)(r0 + 8) * NLIB + c0]) = o1;
        }
    }
}

// ---------------- top-16 candidate selection: one CTA per query ----------------
__global__ void topk_kernel() {
    const int q = blockIdx.x;
    const int tid = threadIdx.x;             // 256 threads
    const float* row = g_d2 + (size_t)q * NLIB;

    float lv[KCAND];
    int   li[KCAND];
#pragma unroll
    for (int s = 0; s < KCAND; ++s) { lv[s] = FLT_MAX; li[s] = 0x7FFFFFFF; }
    float th = FLT_MAX;

    for (int j = tid; j < NLIB; j += 256) {
        float v = row[j];
        if (v < th) {
            int p = KCAND - 1;
            while (p > 0 && lv[p - 1] > v) {
                lv[p] = lv[p - 1]; li[p] = li[p - 1]; --p;
            }
            lv[p] = v; li[p] = j;
            th = lv[KCAND - 1];
        }
    }

    __shared__ float sv[256 * KCAND];
    __shared__ int   si[256 * KCAND];
    __shared__ float rv[256];
    __shared__ int   ri[256];
    __shared__ int   rp[256];
#pragma unroll
    for (int s = 0; s < KCAND; ++s) {
        sv[tid * KCAND + s] = lv[s];
        si[tid * KCAND + s] = li[s];
    }
    __syncthreads();

    for (int r = 0; r < KCAND; ++r) {
        float bv = FLT_MAX; int bi = 0x7FFFFFFF; int bp = tid * KCAND;
#pragma unroll
        for (int s = 0; s < KCAND; ++s) {
            int p = tid * KCAND + s;
            float v = sv[p]; int ix = si[p];
            if (v < bv || (v == bv && ix < bi)) { bv = v; bi = ix; bp = p; }
        }
        rv[tid] = bv; ri[tid] = bi; rp[tid] = bp;
        __syncthreads();
        for (int s = 128; s > 0; s >>= 1) {
            if (tid < s) {
                float v2 = rv[tid + s]; int i2 = ri[tid + s];
                if (v2 < rv[tid] || (v2 == rv[tid] && i2 < ri[tid])) {
                    rv[tid] = v2; ri[tid] = i2; rp[tid] = rp[tid + s];
                }
            }
            __syncthreads();
        }
        if (tid == 0) {
            g_cand[q * KCAND + r] = ri[0];
            sv[rp[0]] = FLT_MAX;
            si[rp[0]] = 0x7FFFFFFF;
        }
        __syncthreads();
    }
}

// ---------------- exact fp32 rerank of 16 candidates ----------------
__global__ void rerank_kernel(const float* __restrict__ Qm, const float* __restrict__ Lm,
                              float* __restrict__ out, int out_size) {
    const int q = blockIdx.x;
    const int wid = threadIdx.x >> 5;
    const int lane = threadIdx.x & 31;
    __shared__ float cv[KCAND];
    __shared__ int   ci[KCAND];

    for (int c = wid; c < KCAND; c += 4) {
        int idx = g_cand[q * KCAND + c];
        const float4* xp = reinterpret_cast<const float4*>(Lm + (size_t)idx * DDIM);
        const float4* qp = reinterpret_cast<const float4*>(Qm + (size_t)q * DDIM);
        float dot = 0.f;
#pragma unroll
        for (int i = lane; i < DDIM / 4; i += 32) {
            float4 a = qp[i], b = xp[i];
            dot = fmaf(a.x, b.x, fmaf(a.y, b.y, fmaf(a.z, b.z, fmaf(a.w, b.w, dot))));
        }
#pragma unroll
        for (int o = 16; o; o >>= 1) dot += __shfl_xor_sync(0xffffffffu, dot, o);
        if (lane == 0) {
            cv[c] = fmaf(-2.f, dot, g_qsq[q] + g_xsq[idx]);
            ci[c] = idx;
        }
    }
    __syncthreads();
    if (threadIdx.x == 0) {
        for (int a = 1; a < KCAND; ++a) {
            float v = cv[a]; int ix = ci[a]; int b = a - 1;
            while (b >= 0 && (cv[b] > v || (cv[b] == v && ci[b] > ix))) {
                cv[b + 1] = cv[b]; ci[b + 1] = ci[b]; --b;
            }
            cv[b + 1] = v; ci[b + 1] = ix;
        }
        for (int r = 0; r < KOUT; ++r) {
            int o = q * KOUT + r;
            if (o < out_size) out[o] = cv[r];
            int o2 = QN * KOUT + q * KOUT + r;
            if (o2 < out_size) out[o2] = (float)ci[r];
        }
    }
}

// ---------------- launch ----------------
extern "C" void kernel_launch(void* const* d_in, const int* in_sizes, int n_in,
                              void* d_out, int out_size) {
    const float* query = (const float*)d_in[0];
    const float* lib   = (const float*)d_in[1];
    float* out = (float*)d_out;

    static int configured = 0;
    if (!configured) {
        cudaFuncSetAttribute(gemm_kernel,
                             cudaFuncAttributeMaxDynamicSharedMemorySize, SMEM_BYTES);
        configured = 1;
    }

    int8_t *qi, *li;
    float *qsq, *xsq;
    cudaGetSymbolAddress((void**)&qi,  g_qi);
    cudaGetSymbolAddress((void**)&li,  g_libi);
    cudaGetSymbolAddress((void**)&qsq, g_qsq);
    cudaGetSymbolAddress((void**)&xsq, g_xsq);

    // fp32 -> int8 quantization fused with exact fp32 row norms
    convert_kernel<<<(QN * 32 + 255) / 256, 256>>>(query, qi, qsq, QN);
    convert_kernel<<<(NLIB * 32 + 255) / 256, 256>>>(lib, li, xsq, NLIB);

    // approx distance matrix (int8 IMMA, s32 accumulate)
    dim3 grid(QN / TM, NLIB / TN);
    gemm_kernel<<<grid, 256, SMEM_BYTES>>>();

    // approx top-16, then exact fp32 rerank -> top-10
    topk_kernel<<<QN, 256>>>();
    rerank_kernel<<<QN, 128>>>(query, lib, out, out_size);
}